// round 1
// baseline (speedup 1.0000x reference)
#include <cuda_runtime.h>
#include <math.h>

#define TILE 128
#define LD   132           // padded smem leading dim (floats)
#define NBLK 64            // attention blocks per batch (first half only)
#define BATCH 8

// Dynamic smem: X tile + A (Q/P) + B (K/T) + weight stage (32 rows)
#define SMEM_FLOATS (3 * TILE * LD + 32 * LD)
#define SMEM_BYTES  (SMEM_FLOATS * 4)

__device__ float g_Wvo[TILE * TILE];   // Wv @ Wo, precomputed per call

// ---------------------------------------------------------------------------
// width-16 reductions: a row-group = 16 consecutive lanes (tid = ty*16 + tx)
// ---------------------------------------------------------------------------
static __device__ __forceinline__ float redmax16(float v) {
#pragma unroll
    for (int off = 8; off > 0; off >>= 1)
        v = fmaxf(v, __shfl_xor_sync(0xffffffffu, v, off, 16));
    return v;
}
static __device__ __forceinline__ float redsum16(float v) {
#pragma unroll
    for (int off = 8; off > 0; off >>= 1)
        v += __shfl_xor_sync(0xffffffffu, v, off, 16);
    return v;
}

// ---------------------------------------------------------------------------
// Wvo = Wv @ Wo   (16 blocks x 256 threads; each thread -> 4 outputs)
// ---------------------------------------------------------------------------
__global__ void wvo_kernel(const float* __restrict__ Wv,
                           const float* __restrict__ Wo) {
    int row = blockIdx.x * 8 + (threadIdx.x >> 5);
    int c4  = (threadIdx.x & 31) * 4;
    float4 acc = make_float4(0.f, 0.f, 0.f, 0.f);
#pragma unroll 4
    for (int k = 0; k < 128; ++k) {
        float  a = Wv[row * 128 + k];
        float4 b = *(const float4*)&Wo[k * 128 + c4];
        acc.x = fmaf(a, b.x, acc.x);
        acc.y = fmaf(a, b.y, acc.y);
        acc.z = fmaf(a, b.z, acc.z);
        acc.w = fmaf(a, b.w, acc.w);
    }
    *(float4*)&g_Wvo[row * 128 + c4] = acc;
}

// ---------------------------------------------------------------------------
// Second half of output: zeros-passer blocks give h == 0 exactly,
// so out = gelu(beta[d]) broadcast. Pure fill.
// ---------------------------------------------------------------------------
__global__ void fill_kernel(const float* __restrict__ beta,
                            float* __restrict__ out) {
    __shared__ float4 gb4[32];
    int t = threadIdx.x;
    if (t < 32) {
        float4 b = ((const float4*)beta)[t];
        float4 g;
        g.x = 0.5f * b.x * (1.f + erff(b.x * 0.70710678118654752f));
        g.y = 0.5f * b.y * (1.f + erff(b.y * 0.70710678118654752f));
        g.z = 0.5f * b.z * (1.f + erff(b.z * 0.70710678118654752f));
        g.w = 0.5f * b.w * (1.f + erff(b.w * 0.70710678118654752f));
        gb4[t] = g;
    }
    __syncthreads();
    const long long total = 8LL * 8192 * 32;       // float4 count, second half
    float4* o4 = (float4*)out;
    for (long long i = (long long)blockIdx.x * blockDim.x + t; i < total;
         i += (long long)gridDim.x * blockDim.x) {
        long long b = i / (8192 * 32);
        long long r = i - b * (8192 * 32);
        o4[(b * 16384 + 8192) * 32 + r] = gb4[(int)(i & 31)];
    }
}

// ---------------------------------------------------------------------------
// GEMM building blocks. C-tile: thread (ty,tx) owns rows ty*8..+8, cols tx*8..+8.
// ---------------------------------------------------------------------------
static __device__ __forceinline__ void zero_acc(float acc[8][8]) {
#pragma unroll
    for (int r = 0; r < 8; ++r)
#pragma unroll
        for (int c = 0; c < 8; ++c) acc[r][c] = 0.f;
}

// acc += A(sm,128xK ld=LD) @ Wg(global 128x128 row-major), staged 32 rows at a time
static __device__ __forceinline__ void gemm_AB_stage(
    const float* __restrict__ Asm, const float* __restrict__ Wg,
    float* __restrict__ wst, float acc[8][8], int ty, int tx, int tid) {
    zero_acc(acc);
    for (int kc = 0; kc < 4; ++kc) {
        __syncthreads();                    // prior wst readers done
        for (int i = tid; i < 1024; i += 256) {
            int r = i >> 5, c4 = i & 31;
            *(float4*)&wst[r * LD + c4 * 4] =
                ((const float4*)Wg)[(kc * 32 + r) * 32 + c4];
        }
        __syncthreads();
        const int kb = kc * 32;
#pragma unroll 2
        for (int k = 0; k < 32; k += 4) {
            float4 av[8];
#pragma unroll
            for (int r = 0; r < 8; ++r)
                av[r] = *(const float4*)&Asm[(ty * 8 + r) * LD + kb + k];
#pragma unroll
            for (int i = 0; i < 4; ++i) {
                float4 b0 = *(const float4*)&wst[(k + i) * LD + tx * 8];
                float4 b1 = *(const float4*)&wst[(k + i) * LD + tx * 8 + 4];
                float bb[8] = {b0.x, b0.y, b0.z, b0.w, b1.x, b1.y, b1.z, b1.w};
#pragma unroll
                for (int r = 0; r < 8; ++r) {
                    float a = ((const float*)&av[r])[i];
#pragma unroll
                    for (int c = 0; c < 8; ++c)
                        acc[r][c] = fmaf(a, bb[c], acc[r][c]);
                }
            }
        }
    }
}

// acc = A(sm, 128x128 ld=LD) @ B(sm, 128x128 ld=LD), both row-major
static __device__ __forceinline__ void gemm_AB(
    const float* __restrict__ Asm, const float* __restrict__ Bsm,
    float acc[8][8], int ty, int tx) {
    zero_acc(acc);
#pragma unroll 2
    for (int k = 0; k < 128; k += 4) {
        float4 av[8];
#pragma unroll
        for (int r = 0; r < 8; ++r)
            av[r] = *(const float4*)&Asm[(ty * 8 + r) * LD + k];
#pragma unroll
        for (int i = 0; i < 4; ++i) {
            float4 b0 = *(const float4*)&Bsm[(k + i) * LD + tx * 8];
            float4 b1 = *(const float4*)&Bsm[(k + i) * LD + tx * 8 + 4];
            float bb[8] = {b0.x, b0.y, b0.z, b0.w, b1.x, b1.y, b1.z, b1.w};
#pragma unroll
            for (int r = 0; r < 8; ++r) {
                float a = ((const float*)&av[r])[i];
#pragma unroll
                for (int c = 0; c < 8; ++c)
                    acc[r][c] = fmaf(a, bb[c], acc[r][c]);
            }
        }
    }
}

// acc = Q @ K^T  (both row-major 128x128 ld=LD; dot-product over k via float4)
static __device__ __forceinline__ void gemm_ABt(
    const float* __restrict__ Qsm, const float* __restrict__ Ksm,
    float acc[8][8], int ty, int tx) {
    zero_acc(acc);
#pragma unroll 2
    for (int k = 0; k < 128; k += 4) {
        float4 qv[8];
#pragma unroll
        for (int r = 0; r < 8; ++r)
            qv[r] = *(const float4*)&Qsm[(ty * 8 + r) * LD + k];
#pragma unroll
        for (int c = 0; c < 8; ++c) {
            float4 kv = *(const float4*)&Ksm[(tx * 8 + c) * LD + k];
#pragma unroll
            for (int r = 0; r < 8; ++r) {
                acc[r][c] = fmaf(qv[r].x, kv.x, acc[r][c]);
                acc[r][c] = fmaf(qv[r].y, kv.y, acc[r][c]);
                acc[r][c] = fmaf(qv[r].z, kv.z, acc[r][c]);
                acc[r][c] = fmaf(qv[r].w, kv.w, acc[r][c]);
            }
        }
    }
}

static __device__ __forceinline__ void store_tile(
    float* __restrict__ dst, const float acc[8][8], int ty, int tx) {
#pragma unroll
    for (int r = 0; r < 8; ++r) {
        *(float4*)&dst[(ty * 8 + r) * LD + tx * 8] =
            make_float4(acc[r][0], acc[r][1], acc[r][2], acc[r][3]);
        *(float4*)&dst[(ty * 8 + r) * LD + tx * 8 + 4] =
            make_float4(acc[r][4], acc[r][5], acc[r][6], acc[r][7]);
    }
}

// ---------------------------------------------------------------------------
// Main fused kernel: one CTA per (batch, 128-token block)
// Q = X Wq; K = X Wk; P = softmax(QK^T/sqrt(D)); H = (P X) Wvo; out = gelu(LN(H))
// ---------------------------------------------------------------------------
__global__ void __launch_bounds__(256, 1) attn_kernel(
    const float* __restrict__ x, const float* __restrict__ Wq,
    const float* __restrict__ Wk, const float* __restrict__ gamma,
    const float* __restrict__ beta, float* __restrict__ out) {
    extern __shared__ float sm[];
    float* smX = sm;                    // 128 x LD : X tile
    float* smA = sm + TILE * LD;        // Q, later P
    float* smB = sm + 2 * TILE * LD;    // K, later T = P@X
    float* wst = sm + 3 * TILE * LD;    // 32 x LD weight stage

    const int tid = threadIdx.x;
    const int tx = tid & 15, ty = tid >> 4;

    // load X tile (coalesced float4)
    const long long base =
        ((long long)blockIdx.y * 8192 + (long long)blockIdx.x * TILE) * TILE;
    const float4* x4 = (const float4*)(x + base);
    for (int i = tid; i < TILE * 32; i += 256) {
        int r = i >> 5, c4 = i & 31;
        *(float4*)&smX[r * LD + c4 * 4] = x4[i];
    }
    __syncthreads();

    float acc[8][8];

    gemm_AB_stage(smX, Wq, wst, acc, ty, tx, tid);   // Q
    store_tile(smA, acc, ty, tx);
    gemm_AB_stage(smX, Wk, wst, acc, ty, tx, tid);   // K (leading sync inside)
    store_tile(smB, acc, ty, tx);
    __syncthreads();

    gemm_ABt(smA, smB, acc, ty, tx);                 // S = Q K^T

    // softmax over each row (128 cols split across 16 lanes x 8 regs)
    const float scale = 0.08838834764831845f;        // 1/sqrt(128)
#pragma unroll
    for (int r = 0; r < 8; ++r) {
        float mx = -1e30f;
#pragma unroll
        for (int c = 0; c < 8; ++c) {
            acc[r][c] *= scale;
            mx = fmaxf(mx, acc[r][c]);
        }
        mx = redmax16(mx);
        float s = 0.f;
#pragma unroll
        for (int c = 0; c < 8; ++c) {
            float e = __expf(acc[r][c] - mx);
            acc[r][c] = e;
            s += e;
        }
        s = redsum16(s);
        float inv = 1.0f / s;
#pragma unroll
        for (int c = 0; c < 8; ++c) acc[r][c] *= inv;
    }
    __syncthreads();                 // everyone done reading Q(smA)/K(smB)
    store_tile(smA, acc, ty, tx);    // P -> smA
    __syncthreads();

    gemm_AB(smA, smX, acc, ty, tx);  // T = P @ X
    store_tile(smB, acc, ty, tx);    // T -> smB (K is dead)

    gemm_AB_stage(smB, g_Wvo, wst, acc, ty, tx, tid);  // H = T @ (Wv Wo)

    // LayerNorm (per token row, over 128 cols) + exact GELU
    float4 g0 = *(const float4*)&gamma[tx * 8];
    float4 g1 = *(const float4*)&gamma[tx * 8 + 4];
    float4 e0 = *(const float4*)&beta[tx * 8];
    float4 e1 = *(const float4*)&beta[tx * 8 + 4];
    const float gg[8] = {g0.x, g0.y, g0.z, g0.w, g1.x, g1.y, g1.z, g1.w};
    const float bb[8] = {e0.x, e0.y, e0.z, e0.w, e1.x, e1.y, e1.z, e1.w};

    float* orow =
        out + (((long long)blockIdx.y * 16384) + (long long)blockIdx.x * TILE) * TILE;
#pragma unroll
    for (int r = 0; r < 8; ++r) {
        float s = 0.f;
#pragma unroll
        for (int c = 0; c < 8; ++c) s += acc[r][c];
        s = redsum16(s);
        float mu = s * (1.0f / 128.0f);
        float q = 0.f;
#pragma unroll
        for (int c = 0; c < 8; ++c) {
            float d = acc[r][c] - mu;
            q += d * d;
        }
        q = redsum16(q);
        float rstd = rsqrtf(q * (1.0f / 128.0f) + 1e-5f);
        float o[8];
#pragma unroll
        for (int c = 0; c < 8; ++c) {
            float y = (acc[r][c] - mu) * rstd * gg[c] + bb[c];
            o[c] = 0.5f * y * (1.f + erff(y * 0.70710678118654752f));
        }
        int row = ty * 8 + r;
        *(float4*)&orow[row * 128 + tx * 8] = make_float4(o[0], o[1], o[2], o[3]);
        *(float4*)&orow[row * 128 + tx * 8 + 4] =
            make_float4(o[4], o[5], o[6], o[7]);
    }
}

// ---------------------------------------------------------------------------
extern "C" void kernel_launch(void* const* d_in, const int* in_sizes, int n_in,
                              void* d_out, int out_size) {
    const float* x     = (const float*)d_in[0];
    const float* Wq    = (const float*)d_in[1];
    const float* Wk    = (const float*)d_in[2];
    const float* Wv    = (const float*)d_in[3];
    const float* Wo    = (const float*)d_in[4];
    const float* gamma = (const float*)d_in[5];
    const float* beta  = (const float*)d_in[6];
    float* out = (float*)d_out;

    cudaFuncSetAttribute(attn_kernel,
                         cudaFuncAttributeMaxDynamicSharedMemorySize, SMEM_BYTES);

    wvo_kernel<<<16, 256>>>(Wv, Wo);
    fill_kernel<<<2048, 256>>>(beta, out);
    attn_kernel<<<dim3(NBLK, BATCH), 256, SMEM_BYTES>>>(x, Wq, Wk, gamma, beta, out);
}

// round 3
// speedup vs baseline: 2.2279x; 2.2279x over previous
#include <cuda_runtime.h>
#include <cuda_bf16.h>
#include <math.h>
#include <stdint.h>

#define PITCH 136                 // bf16 elements per smem row (272B)
#define MATB  (128 * PITCH * 2)   // 34816 bytes per 128x128 bf16 matrix

// ---- smem layout (byte offsets) ----
#define XH_OFF 0
#define XL_OFF 34816
#define KH_OFF 69632
#define KL_OFF 104448
#define WH_OFF 139264
#define WL_OFF 174080
#define GB_OFF 208896             // gamma[128] f32, beta[128] f32
#define SMEM_BYTES (208896 + 1024)

// ---- global scratch ----
__device__ float g_Wvo[128 * 128];
__device__ __align__(16) unsigned short g_wh[3][128 * PITCH];  // [n][k] hi
__device__ __align__(16) unsigned short g_wl[3][128 * PITCH];  // [n][k] lo

// ---------------------------------------------------------------------------
static __device__ __forceinline__ void split2(float a, float b,
                                              uint32_t& hi, uint32_t& lo) {
    __nv_bfloat16 ha = __float2bfloat16(a), hb = __float2bfloat16(b);
    float ra = a - __bfloat162float(ha);
    float rb = b - __bfloat162float(hb);
    __nv_bfloat16 la = __float2bfloat16(ra), lb = __float2bfloat16(rb);
    hi = ((uint32_t)__bfloat16_as_ushort(hb) << 16) | __bfloat16_as_ushort(ha);
    lo = ((uint32_t)__bfloat16_as_ushort(lb) << 16) | __bfloat16_as_ushort(la);
}

static __device__ __forceinline__ void mma_bf16(float c[4], uint32_t a0,
                                                uint32_t a1, uint32_t a2,
                                                uint32_t a3, uint32_t b0,
                                                uint32_t b1) {
    asm volatile(
        "mma.sync.aligned.m16n8k16.row.col.f32.bf16.bf16.f32 "
        "{%0,%1,%2,%3}, {%4,%5,%6,%7}, {%8,%9}, {%0,%1,%2,%3};"
        : "+f"(c[0]), "+f"(c[1]), "+f"(c[2]), "+f"(c[3])
        : "r"(a0), "r"(a1), "r"(a2), "r"(a3), "r"(b0), "r"(b1));
}

static __device__ __forceinline__ uint32_t lds32(const unsigned short* p) {
    return *(const uint32_t*)p;
}

// acc = 0
static __device__ __forceinline__ void zero_acc(float acc[16][4]) {
#pragma unroll
    for (int j = 0; j < 16; ++j)
#pragma unroll
        for (int i = 0; i < 4; ++i) acc[j][i] = 0.f;
}

// acc = A(smem bf16 hi/lo, row-major [m][k]) @ B(smem bf16 hi/lo, [n][k])
static __device__ __forceinline__ void gemm_sAB(
    const unsigned short* AH, const unsigned short* AL,
    const unsigned short* BH, const unsigned short* BL, int R, int g, int t,
    float acc[16][4]) {
    zero_acc(acc);
#pragma unroll
    for (int kk = 0; kk < 8; ++kk) {
        const int ac = kk * 16 + 2 * t;
        uint32_t ah0 = lds32(&AH[(R + g) * PITCH + ac]);
        uint32_t ah1 = lds32(&AH[(R + g + 8) * PITCH + ac]);
        uint32_t ah2 = lds32(&AH[(R + g) * PITCH + ac + 8]);
        uint32_t ah3 = lds32(&AH[(R + g + 8) * PITCH + ac + 8]);
        uint32_t al0 = lds32(&AL[(R + g) * PITCH + ac]);
        uint32_t al1 = lds32(&AL[(R + g + 8) * PITCH + ac]);
        uint32_t al2 = lds32(&AL[(R + g) * PITCH + ac + 8]);
        uint32_t al3 = lds32(&AL[(R + g + 8) * PITCH + ac + 8]);
#pragma unroll
        for (int j = 0; j < 16; ++j) {
            const unsigned short* bh = &BH[(8 * j + g) * PITCH + ac];
            const unsigned short* bl = &BL[(8 * j + g) * PITCH + ac];
            uint32_t bh0 = lds32(bh), bh1 = lds32(bh + 8);
            uint32_t bl0 = lds32(bl), bl1 = lds32(bl + 8);
            mma_bf16(acc[j], ah0, ah1, ah2, ah3, bh0, bh1);
            mma_bf16(acc[j], ah0, ah1, ah2, ah3, bl0, bl1);
            mma_bf16(acc[j], al0, al1, al2, al3, bh0, bh1);
        }
    }
}

// acc = A(register frags hi/lo) @ B(smem bf16 hi/lo, [n][k])
static __device__ __forceinline__ void gemm_rAB(
    const uint32_t* Ah, const uint32_t* Al, const unsigned short* BH,
    const unsigned short* BL, int g, int t, float acc[16][4]) {
    zero_acc(acc);
#pragma unroll
    for (int kk = 0; kk < 8; ++kk) {
        const int ac = kk * 16 + 2 * t;
        uint32_t ah0 = Ah[4 * kk], ah1 = Ah[4 * kk + 1], ah2 = Ah[4 * kk + 2],
                 ah3 = Ah[4 * kk + 3];
        uint32_t al0 = Al[4 * kk], al1 = Al[4 * kk + 1], al2 = Al[4 * kk + 2],
                 al3 = Al[4 * kk + 3];
#pragma unroll
        for (int j = 0; j < 16; ++j) {
            const unsigned short* bh = &BH[(8 * j + g) * PITCH + ac];
            const unsigned short* bl = &BL[(8 * j + g) * PITCH + ac];
            uint32_t bh0 = lds32(bh), bh1 = lds32(bh + 8);
            uint32_t bl0 = lds32(bl), bl1 = lds32(bl + 8);
            mma_bf16(acc[j], ah0, ah1, ah2, ah3, bh0, bh1);
            mma_bf16(acc[j], ah0, ah1, ah2, ah3, bl0, bl1);
            mma_bf16(acc[j], al0, al1, al2, al3, bh0, bh1);
        }
    }
}

// acc = A(register frags) @ B where B = X stored row-major [k][n] (strided u16)
static __device__ __forceinline__ void gemm_rA_Bt(
    const uint32_t* Ah, const uint32_t* Al, const unsigned short* XH,
    const unsigned short* XL, int g, int t, float acc[16][4]) {
    zero_acc(acc);
#pragma unroll
    for (int kk = 0; kk < 8; ++kk) {
        const int k0 = kk * 16 + 2 * t;
        uint32_t ah0 = Ah[4 * kk], ah1 = Ah[4 * kk + 1], ah2 = Ah[4 * kk + 2],
                 ah3 = Ah[4 * kk + 3];
        uint32_t al0 = Al[4 * kk], al1 = Al[4 * kk + 1], al2 = Al[4 * kk + 2],
                 al3 = Al[4 * kk + 3];
#pragma unroll
        for (int j = 0; j < 16; ++j) {
            const int col = 8 * j + g;
            uint32_t bh0 = (uint32_t)XH[k0 * PITCH + col] |
                           ((uint32_t)XH[(k0 + 1) * PITCH + col] << 16);
            uint32_t bh1 = (uint32_t)XH[(k0 + 8) * PITCH + col] |
                           ((uint32_t)XH[(k0 + 9) * PITCH + col] << 16);
            uint32_t bl0 = (uint32_t)XL[k0 * PITCH + col] |
                           ((uint32_t)XL[(k0 + 1) * PITCH + col] << 16);
            uint32_t bl1 = (uint32_t)XL[(k0 + 8) * PITCH + col] |
                           ((uint32_t)XL[(k0 + 9) * PITCH + col] << 16);
            mma_bf16(acc[j], ah0, ah1, ah2, ah3, bh0, bh1);
            mma_bf16(acc[j], ah0, ah1, ah2, ah3, bl0, bl1);
            mma_bf16(acc[j], al0, al1, al2, al3, bh0, bh1);
        }
    }
}

// C fragments -> A fragments (hi/lo) of the next GEMM (pure register op)
static __device__ __forceinline__ void to_afrag(const float acc[16][4],
                                                uint32_t* Ah, uint32_t* Al) {
#pragma unroll
    for (int kk = 0; kk < 8; ++kk) {
        split2(acc[2 * kk][0], acc[2 * kk][1], Ah[4 * kk + 0], Al[4 * kk + 0]);
        split2(acc[2 * kk][2], acc[2 * kk][3], Ah[4 * kk + 1], Al[4 * kk + 1]);
        split2(acc[2 * kk + 1][0], acc[2 * kk + 1][1], Ah[4 * kk + 2],
               Al[4 * kk + 2]);
        split2(acc[2 * kk + 1][2], acc[2 * kk + 1][3], Ah[4 * kk + 3],
               Al[4 * kk + 3]);
    }
}

// ---------------------------------------------------------------------------
// Wvo = Wv @ Wo
// ---------------------------------------------------------------------------
__global__ void wvo_kernel(const float* __restrict__ Wv,
                           const float* __restrict__ Wo) {
    __shared__ float wv[128];
    int r = blockIdx.x, n = threadIdx.x;
    wv[n] = Wv[r * 128 + n];
    __syncthreads();
    float acc = 0.f;
#pragma unroll 8
    for (int k = 0; k < 128; ++k) acc = fmaf(wv[k], Wo[k * 128 + n], acc);
    g_Wvo[r * 128 + n] = acc;
}

// ---------------------------------------------------------------------------
// Split weights -> transposed [n][k] pitched bf16 hi/lo (Wq pre-scaled)
// ---------------------------------------------------------------------------
__global__ void prep_kernel(const float* __restrict__ Wq,
                            const float* __restrict__ Wk) {
    int m = blockIdx.x, n = threadIdx.x;
    const float* src = (m == 0) ? Wq : (m == 1) ? Wk : g_Wvo;
    float scale = (m == 0) ? 0.08838834764831845f : 1.0f;
    for (int k = 0; k < 128; ++k) {
        float w = src[k * 128 + n] * scale;
        __nv_bfloat16 h = __float2bfloat16(w);
        float r = w - __bfloat162float(h);
        __nv_bfloat16 l = __float2bfloat16(r);
        g_wh[m][n * PITCH + k] = __bfloat16_as_ushort(h);
        g_wl[m][n * PITCH + k] = __bfloat16_as_ushort(l);
    }
}

// ---------------------------------------------------------------------------
// Second half of output = gelu(beta) broadcast (zeros-passer blocks give h=0)
// ---------------------------------------------------------------------------
__global__ void fill_kernel(const float* __restrict__ beta,
                            float* __restrict__ out) {
    __shared__ float4 gb4[32];
    int t = threadIdx.x;
    if (t < 32) {
        float4 b = ((const float4*)beta)[t];
        float4 g;
        g.x = 0.5f * b.x * (1.f + erff(b.x * 0.70710678118654752f));
        g.y = 0.5f * b.y * (1.f + erff(b.y * 0.70710678118654752f));
        g.z = 0.5f * b.z * (1.f + erff(b.z * 0.70710678118654752f));
        g.w = 0.5f * b.w * (1.f + erff(b.w * 0.70710678118654752f));
        gb4[t] = g;
    }
    __syncthreads();
    const long long total = 8LL * 8192 * 32;
    float4* o4 = (float4*)out;
    for (long long i = (long long)blockIdx.x * blockDim.x + t; i < total;
         i += (long long)gridDim.x * blockDim.x) {
        long long b = i / (8192 * 32);
        long long r = i - b * (8192 * 32);
        o4[(b * 16384 + 8192) * 32 + r] = gb4[(int)(i & 31)];
    }
}

// ---------------------------------------------------------------------------
// Main fused kernel: one CTA per 128-token block, 256 threads (8 warps).
// Warp w owns output rows [16w, 16w+16).
// ---------------------------------------------------------------------------
__global__ void __launch_bounds__(256, 1) attn_kernel(
    const float* __restrict__ x, const float* __restrict__ gamma,
    const float* __restrict__ beta, float* __restrict__ out) {
    extern __shared__ char smc[];
    unsigned short* XH = (unsigned short*)(smc + XH_OFF);
    unsigned short* XL = (unsigned short*)(smc + XL_OFF);
    unsigned short* KH = (unsigned short*)(smc + KH_OFF);
    unsigned short* KL = (unsigned short*)(smc + KL_OFF);
    unsigned short* WH = (unsigned short*)(smc + WH_OFF);
    unsigned short* WL = (unsigned short*)(smc + WL_OFF);
    float* sgam = (float*)(smc + GB_OFF);
    float* sbet = sgam + 128;

    const int tid = threadIdx.x;
    const int lane = tid & 31;
    const int w = tid >> 5;
    const int g = lane >> 2, t = lane & 3;
    const int R = 16 * w;

    if (tid < 128) {
        sgam[tid] = gamma[tid];
        sbet[tid] = beta[tid];
    }

    // load X tile -> bf16 hi/lo pitched smem
    {
        const long long base =
            ((long long)blockIdx.y * 8192 + (long long)blockIdx.x * 128) * 128;
        const int row = tid >> 1, c0 = (tid & 1) * 64;
        const float4* xg = (const float4*)(x + base + row * 128 + c0);
#pragma unroll
        for (int i = 0; i < 16; ++i) {
            float4 f = xg[i];
            uint32_t h0, l0, h1, l1;
            split2(f.x, f.y, h0, l0);
            split2(f.z, f.w, h1, l1);
            *(uint32_t*)&XH[row * PITCH + c0 + 4 * i] = h0;
            *(uint32_t*)&XH[row * PITCH + c0 + 4 * i + 2] = h1;
            *(uint32_t*)&XL[row * PITCH + c0 + 4 * i] = l0;
            *(uint32_t*)&XL[row * PITCH + c0 + 4 * i + 2] = l1;
        }
    }
    // stage Wq
    {
        const uint4* gh = (const uint4*)g_wh[0];
        const uint4* gl = (const uint4*)g_wl[0];
        uint4* dh = (uint4*)WH;
        uint4* dl = (uint4*)WL;
        for (int i = tid; i < 2176; i += 256) {
            dh[i] = gh[i];
            dl[i] = gl[i];
        }
    }
    __syncthreads();

    float acc[16][4];
    uint32_t Ah[32], Al[32];

    // ---- Q = X @ Wq' (scale folded) ----
    gemm_sAB(XH, XL, WH, WL, R, g, t, acc);
    to_afrag(acc, Ah, Al);  // Q frags
    __syncthreads();
    // stage Wk
    {
        const uint4* gh = (const uint4*)g_wh[1];
        const uint4* gl = (const uint4*)g_wl[1];
        uint4* dh = (uint4*)WH;
        uint4* dl = (uint4*)WL;
        for (int i = tid; i < 2176; i += 256) {
            dh[i] = gh[i];
            dl[i] = gl[i];
        }
    }
    __syncthreads();

    // ---- K = X @ Wk ----
    gemm_sAB(XH, XL, WH, WL, R, g, t, acc);
    // store K (bf16 hi/lo, row-major [tok][d])
#pragma unroll
    for (int j = 0; j < 16; ++j) {
        const int col = 8 * j + 2 * t;
        uint32_t h, l;
        split2(acc[j][0], acc[j][1], h, l);
        *(uint32_t*)&KH[(R + g) * PITCH + col] = h;
        *(uint32_t*)&KL[(R + g) * PITCH + col] = l;
        split2(acc[j][2], acc[j][3], h, l);
        *(uint32_t*)&KH[(R + g + 8) * PITCH + col] = h;
        *(uint32_t*)&KL[(R + g + 8) * PITCH + col] = l;
    }
    __syncthreads();
    // stage Wvo
    {
        const uint4* gh = (const uint4*)g_wh[2];
        const uint4* gl = (const uint4*)g_wl[2];
        uint4* dh = (uint4*)WH;
        uint4* dl = (uint4*)WL;
        for (int i = tid; i < 2176; i += 256) {
            dh[i] = gh[i];
            dl[i] = gl[i];
        }
    }
    __syncthreads();

    // ---- S = Q @ K^T (K row-major [tok][d] == B col-major) ----
    gemm_rAB(Ah, Al, KH, KL, g, t, acc);

    // ---- softmax per row (row r spread over 4 lanes x 32 vals) ----
    {
        float mx0 = -1e30f, mx1 = -1e30f;
#pragma unroll
        for (int j = 0; j < 16; ++j) {
            mx0 = fmaxf(mx0, fmaxf(acc[j][0], acc[j][1]));
            mx1 = fmaxf(mx1, fmaxf(acc[j][2], acc[j][3]));
        }
        mx0 = fmaxf(mx0, __shfl_xor_sync(0xffffffffu, mx0, 1));
        mx0 = fmaxf(mx0, __shfl_xor_sync(0xffffffffu, mx0, 2));
        mx1 = fmaxf(mx1, __shfl_xor_sync(0xffffffffu, mx1, 1));
        mx1 = fmaxf(mx1, __shfl_xor_sync(0xffffffffu, mx1, 2));
        float s0 = 0.f, s1 = 0.f;
#pragma unroll
        for (int j = 0; j < 16; ++j) {
            acc[j][0] = __expf(acc[j][0] - mx0);
            acc[j][1] = __expf(acc[j][1] - mx0);
            acc[j][2] = __expf(acc[j][2] - mx1);
            acc[j][3] = __expf(acc[j][3] - mx1);
            s0 += acc[j][0] + acc[j][1];
            s1 += acc[j][2] + acc[j][3];
        }
        s0 += __shfl_xor_sync(0xffffffffu, s0, 1);
        s0 += __shfl_xor_sync(0xffffffffu, s0, 2);
        s1 += __shfl_xor_sync(0xffffffffu, s1, 1);
        s1 += __shfl_xor_sync(0xffffffffu, s1, 2);
        float i0 = 1.0f / s0, i1 = 1.0f / s1;
#pragma unroll
        for (int j = 0; j < 16; ++j) {
            acc[j][0] *= i0;
            acc[j][1] *= i0;
            acc[j][2] *= i1;
            acc[j][3] *= i1;
        }
    }
    to_afrag(acc, Ah, Al);  // P frags

    // ---- T = P @ X (B = X row-major [tok][d], strided u16 loads) ----
    gemm_rA_Bt(Ah, Al, XH, XL, g, t, acc);
    to_afrag(acc, Ah, Al);  // T frags

    // ---- H = T @ Wvo ----
    gemm_rAB(Ah, Al, WH, WL, g, t, acc);

    // ---- LayerNorm + exact GELU + store ----
    {
        float s0 = 0.f, s1 = 0.f;
#pragma unroll
        for (int j = 0; j < 16; ++j) {
            s0 += acc[j][0] + acc[j][1];
            s1 += acc[j][2] + acc[j][3];
        }
        s0 += __shfl_xor_sync(0xffffffffu, s0, 1);
        s0 += __shfl_xor_sync(0xffffffffu, s0, 2);
        s1 += __shfl_xor_sync(0xffffffffu, s1, 1);
        s1 += __shfl_xor_sync(0xffffffffu, s1, 2);
        float mu0 = s0 * (1.0f / 128.0f), mu1 = s1 * (1.0f / 128.0f);
        float q0 = 0.f, q1 = 0.f;
#pragma unroll
        for (int j = 0; j < 16; ++j) {
            float d0 = acc[j][0] - mu0, d1 = acc[j][1] - mu0;
            float d2 = acc[j][2] - mu1, d3 = acc[j][3] - mu1;
            q0 += d0 * d0 + d1 * d1;
            q1 += d2 * d2 + d3 * d3;
        }
        q0 += __shfl_xor_sync(0xffffffffu, q0, 1);
        q0 += __shfl_xor_sync(0xffffffffu, q0, 2);
        q1 += __shfl_xor_sync(0xffffffffu, q1, 1);
        q1 += __shfl_xor_sync(0xffffffffu, q1, 2);
        float r0 = rsqrtf(q0 * (1.0f / 128.0f) + 1e-5f);
        float r1 = rsqrtf(q1 * (1.0f / 128.0f) + 1e-5f);

        float* orow = out + ((long long)blockIdx.y * 16384 +
                             (long long)blockIdx.x * 128 + R + g) * 128;
        float* orow8 = orow + 8 * 128;
#pragma unroll
        for (int j = 0; j < 16; ++j) {
            const int col = 8 * j + 2 * t;
            float ga0 = sgam[col], ga1 = sgam[col + 1];
            float be0 = sbet[col], be1 = sbet[col + 1];
            float y0 = (acc[j][0] - mu0) * r0 * ga0 + be0;
            float y1 = (acc[j][1] - mu0) * r0 * ga1 + be1;
            float y2 = (acc[j][2] - mu1) * r1 * ga0 + be0;
            float y3 = (acc[j][3] - mu1) * r1 * ga1 + be1;
            float2 o0, o1;
            o0.x = 0.5f * y0 * (1.f + erff(y0 * 0.70710678118654752f));
            o0.y = 0.5f * y1 * (1.f + erff(y1 * 0.70710678118654752f));
            o1.x = 0.5f * y2 * (1.f + erff(y2 * 0.70710678118654752f));
            o1.y = 0.5f * y3 * (1.f + erff(y3 * 0.70710678118654752f));
            *(float2*)&orow[col] = o0;
            *(float2*)&orow8[col] = o1;
        }
    }
}

// ---------------------------------------------------------------------------
extern "C" void kernel_launch(void* const* d_in, const int* in_sizes, int n_in,
                              void* d_out, int out_size) {
    const float* x     = (const float*)d_in[0];
    const float* Wq    = (const float*)d_in[1];
    const float* Wk    = (const float*)d_in[2];
    const float* Wv    = (const float*)d_in[3];
    const float* Wo    = (const float*)d_in[4];
    const float* gamma = (const float*)d_in[5];
    const float* beta  = (const float*)d_in[6];
    float* out = (float*)d_out;

    cudaFuncSetAttribute(attn_kernel,
                         cudaFuncAttributeMaxDynamicSharedMemorySize, SMEM_BYTES);

    wvo_kernel<<<128, 128>>>(Wv, Wo);
    prep_kernel<<<3, 128>>>(Wq, Wk);
    fill_kernel<<<2048, 256>>>(beta, out);
    attn_kernel<<<dim3(64, 8), 256, SMEM_BYTES>>>(x, gamma, beta, out);
}

// round 4
// speedup vs baseline: 3.0888x; 1.3864x over previous
#include <cuda_runtime.h>
#include <cuda_bf16.h>
#include <math.h>
#include <stdint.h>

#define PITCH 136                 // bf16 elements per smem row (272B)

// ---- smem layout (byte offsets) ----
#define XH_OFF  0
#define XL_OFF  34816
#define W2H_OFF 69632             // Wk, later Wvo
#define W2L_OFF 104448
#define W1H_OFF 139264            // Wq, later K
#define W1L_OFF 174080
#define GB_OFF  208896            // gamma[128] f32, beta[128] f32
#define SMEM_BYTES (208896 + 1024)

// ---- global scratch ----
__device__ float g_Wvo[128 * 128];
__device__ __align__(16) unsigned short g_wh[3][128 * PITCH];  // [n][k] hi
__device__ __align__(16) unsigned short g_wl[3][128 * PITCH];  // [n][k] lo

// ---------------------------------------------------------------------------
static __device__ __forceinline__ uint32_t smem_u32(const void* p) {
    uint32_t a;
    asm("{ .reg .u64 t; cvta.to.shared.u64 t, %1; cvt.u32.u64 %0, t; }"
        : "=r"(a) : "l"(p));
    return a;
}

static __device__ __forceinline__ void cp16(uint32_t dst, const void* src) {
    asm volatile("cp.async.cg.shared.global [%0], [%1], 16;"
                 :: "r"(dst), "l"(src) : "memory");
}
#define CP_COMMIT() asm volatile("cp.async.commit_group;" ::: "memory")
#define CP_WAIT0()  asm volatile("cp.async.wait_group 0;" ::: "memory")

static __device__ __forceinline__ void split2(float a, float b,
                                              uint32_t& hi, uint32_t& lo) {
    __nv_bfloat16 ha = __float2bfloat16(a), hb = __float2bfloat16(b);
    float ra = a - __bfloat162float(ha);
    float rb = b - __bfloat162float(hb);
    __nv_bfloat16 la = __float2bfloat16(ra), lb = __float2bfloat16(rb);
    hi = ((uint32_t)__bfloat16_as_ushort(hb) << 16) | __bfloat16_as_ushort(ha);
    lo = ((uint32_t)__bfloat16_as_ushort(lb) << 16) | __bfloat16_as_ushort(la);
}

static __device__ __forceinline__ void mma_bf16(float c[4], uint32_t a0,
                                                uint32_t a1, uint32_t a2,
                                                uint32_t a3, uint32_t b0,
                                                uint32_t b1) {
    asm volatile(
        "mma.sync.aligned.m16n8k16.row.col.f32.bf16.bf16.f32 "
        "{%0,%1,%2,%3}, {%4,%5,%6,%7}, {%8,%9}, {%0,%1,%2,%3};"
        : "+f"(c[0]), "+f"(c[1]), "+f"(c[2]), "+f"(c[3])
        : "r"(a0), "r"(a1), "r"(a2), "r"(a3), "r"(b0), "r"(b1));
}

static __device__ __forceinline__ void ldsm4(uint32_t& r0, uint32_t& r1,
                                             uint32_t& r2, uint32_t& r3,
                                             uint32_t addr) {
    asm volatile("ldmatrix.sync.aligned.m8n8.x4.shared.b16 {%0,%1,%2,%3}, [%4];"
                 : "=r"(r0), "=r"(r1), "=r"(r2), "=r"(r3) : "r"(addr));
}
static __device__ __forceinline__ void ldsm4t(uint32_t& r0, uint32_t& r1,
                                              uint32_t& r2, uint32_t& r3,
                                              uint32_t addr) {
    asm volatile(
        "ldmatrix.sync.aligned.m8n8.x4.trans.shared.b16 {%0,%1,%2,%3}, [%4];"
        : "=r"(r0), "=r"(r1), "=r"(r2), "=r"(r3) : "r"(addr));
}

static __device__ __forceinline__ void zero_acc(float acc[16][4]) {
#pragma unroll
    for (int j = 0; j < 16; ++j)
#pragma unroll
        for (int i = 0; i < 4; ++i) acc[j][i] = 0.f;
}

// 3-pass MMA bundle for a j-pair given A-frags (hi/lo) and B-frags (hi b, lo c)
static __device__ __forceinline__ void mma_jp(float a0[4], float a1[4],
                                              const uint32_t ah[4],
                                              const uint32_t al[4],
                                              uint32_t b0, uint32_t b1,
                                              uint32_t b2, uint32_t b3,
                                              uint32_t c0, uint32_t c1,
                                              uint32_t c2, uint32_t c3) {
    mma_bf16(a0, ah[0], ah[1], ah[2], ah[3], b0, b1);
    mma_bf16(a1, ah[0], ah[1], ah[2], ah[3], b2, b3);
    mma_bf16(a0, ah[0], ah[1], ah[2], ah[3], c0, c1);
    mma_bf16(a1, ah[0], ah[1], ah[2], ah[3], c2, c3);
    mma_bf16(a0, al[0], al[1], al[2], al[3], b0, b1);
    mma_bf16(a1, al[0], al[1], al[2], al[3], b2, b3);
}

// acc = A(smem, ldmatrix) @ B(smem [n][k], ldmatrix)
static __device__ __forceinline__ void gemm_sAB(uint32_t aH, uint32_t aL,
                                                uint32_t bH, uint32_t bL,
                                                float acc[16][4]) {
    zero_acc(acc);
#pragma unroll
    for (int kk = 0; kk < 8; ++kk) {
        uint32_t ah[4], al[4];
        ldsm4(ah[0], ah[1], ah[2], ah[3], aH + kk * 32);
        ldsm4(al[0], al[1], al[2], al[3], aL + kk * 32);
#pragma unroll
        for (int jp = 0; jp < 8; ++jp) {
            uint32_t o = (uint32_t)(jp * 16 * PITCH + kk * 16) * 2;
            uint32_t b0, b1, b2, b3, c0, c1, c2, c3;
            ldsm4(b0, b1, b2, b3, bH + o);
            ldsm4(c0, c1, c2, c3, bL + o);
            mma_jp(acc[2 * jp], acc[2 * jp + 1], ah, al, b0, b1, b2, b3, c0,
                   c1, c2, c3);
        }
    }
}

// acc = A(register frags) @ B(smem [n][k], ldmatrix)
static __device__ __forceinline__ void gemm_rAB(const uint32_t* Ah,
                                                const uint32_t* Al,
                                                uint32_t bH, uint32_t bL,
                                                float acc[16][4]) {
    zero_acc(acc);
#pragma unroll
    for (int kk = 0; kk < 8; ++kk) {
#pragma unroll
        for (int jp = 0; jp < 8; ++jp) {
            uint32_t o = (uint32_t)(jp * 16 * PITCH + kk * 16) * 2;
            uint32_t b0, b1, b2, b3, c0, c1, c2, c3;
            ldsm4(b0, b1, b2, b3, bH + o);
            ldsm4(c0, c1, c2, c3, bL + o);
            mma_jp(acc[2 * jp], acc[2 * jp + 1], &Ah[4 * kk], &Al[4 * kk], b0,
                   b1, b2, b3, c0, c1, c2, c3);
        }
    }
}

// acc = A(register frags) @ X (smem row-major [tok][d], ldmatrix.trans)
static __device__ __forceinline__ void gemm_rTX(const uint32_t* Ah,
                                                const uint32_t* Al,
                                                uint32_t xH, uint32_t xL,
                                                float acc[16][4]) {
    zero_acc(acc);
#pragma unroll
    for (int kk = 0; kk < 8; ++kk) {
#pragma unroll
        for (int jp = 0; jp < 8; ++jp) {
            uint32_t o = (uint32_t)(kk * 16 * PITCH + jp * 16) * 2;
            uint32_t b0, b1, b2, b3, c0, c1, c2, c3;
            ldsm4t(b0, b1, b2, b3, xH + o);
            ldsm4t(c0, c1, c2, c3, xL + o);
            mma_jp(acc[2 * jp], acc[2 * jp + 1], &Ah[4 * kk], &Al[4 * kk], b0,
                   b1, b2, b3, c0, c1, c2, c3);
        }
    }
}

// C fragments -> A fragments (hi/lo) of next GEMM (pure register op)
static __device__ __forceinline__ void to_afrag(const float acc[16][4],
                                                uint32_t* Ah, uint32_t* Al) {
#pragma unroll
    for (int kk = 0; kk < 8; ++kk) {
        split2(acc[2 * kk][0], acc[2 * kk][1], Ah[4 * kk + 0], Al[4 * kk + 0]);
        split2(acc[2 * kk][2], acc[2 * kk][3], Ah[4 * kk + 1], Al[4 * kk + 1]);
        split2(acc[2 * kk + 1][0], acc[2 * kk + 1][1], Ah[4 * kk + 2],
               Al[4 * kk + 2]);
        split2(acc[2 * kk + 1][2], acc[2 * kk + 1][3], Ah[4 * kk + 3],
               Al[4 * kk + 3]);
    }
}

// ---------------------------------------------------------------------------
__global__ void wvo_kernel(const float* __restrict__ Wv,
                           const float* __restrict__ Wo) {
    __shared__ float wv[128];
    int r = blockIdx.x, n = threadIdx.x;
    wv[n] = Wv[r * 128 + n];
    __syncthreads();
    float acc = 0.f;
#pragma unroll 8
    for (int k = 0; k < 128; ++k) acc = fmaf(wv[k], Wo[k * 128 + n], acc);
    g_Wvo[r * 128 + n] = acc;
}

__global__ void prep_kernel(const float* __restrict__ Wq,
                            const float* __restrict__ Wk) {
    int m = blockIdx.x, n = threadIdx.x;
    const float* src = (m == 0) ? Wq : (m == 1) ? Wk : g_Wvo;
    float scale = (m == 0) ? 0.08838834764831845f : 1.0f;
    for (int k = 0; k < 128; ++k) {
        float w = src[k * 128 + n] * scale;
        __nv_bfloat16 h = __float2bfloat16(w);
        float r = w - __bfloat162float(h);
        __nv_bfloat16 l = __float2bfloat16(r);
        g_wh[m][n * PITCH + k] = __bfloat16_as_ushort(h);
        g_wl[m][n * PITCH + k] = __bfloat16_as_ushort(l);
    }
}

__global__ void fill_kernel(const float* __restrict__ beta,
                            float* __restrict__ out) {
    __shared__ float4 gb4[32];
    int t = threadIdx.x;
    if (t < 32) {
        float4 b = ((const float4*)beta)[t];
        float4 g;
        g.x = 0.5f * b.x * (1.f + erff(b.x * 0.70710678118654752f));
        g.y = 0.5f * b.y * (1.f + erff(b.y * 0.70710678118654752f));
        g.z = 0.5f * b.z * (1.f + erff(b.z * 0.70710678118654752f));
        g.w = 0.5f * b.w * (1.f + erff(b.w * 0.70710678118654752f));
        gb4[t] = g;
    }
    __syncthreads();
    const long long total = 8LL * 8192 * 32;
    float4* o4 = (float4*)out;
    for (long long i = (long long)blockIdx.x * blockDim.x + t; i < total;
         i += (long long)gridDim.x * blockDim.x) {
        long long b = i / (8192 * 32);
        long long r = i - b * (8192 * 32);
        o4[(b * 16384 + 8192) * 32 + r] = gb4[(int)(i & 31)];
    }
}

// ---------------------------------------------------------------------------
// Main fused kernel: one CTA per 128-token block, 256 threads (8 warps).
// Warp w owns output rows [16w, 16w+16).
// ---------------------------------------------------------------------------
__global__ void __launch_bounds__(256, 1) attn_kernel(
    const float* __restrict__ x, const float* __restrict__ gamma,
    const float* __restrict__ beta, float* __restrict__ out) {
    extern __shared__ char smc[];
    const int tid = threadIdx.x;
    const int lane = tid & 31;
    const int w = tid >> 5;
    const int g = lane >> 2, t = lane & 3;
    const int R = 16 * w;

    const uint32_t xh_u = smem_u32(smc + XH_OFF);
    const uint32_t xl_u = smem_u32(smc + XL_OFF);
    const uint32_t w1h_u = smem_u32(smc + W1H_OFF);
    const uint32_t w1l_u = smem_u32(smc + W1L_OFF);
    const uint32_t w2h_u = smem_u32(smc + W2H_OFF);
    const uint32_t w2l_u = smem_u32(smc + W2L_OFF);

    // ldmatrix lane offsets (elements)
    const int L = lane;
    const uint32_t offA =
        (uint32_t)(((L & 7) + (L & 8)) * PITCH + ((L & 16) ? 8 : 0)) * 2;
    const uint32_t offB =
        (uint32_t)(((L & 7) + ((L & 16) ? 8 : 0)) * PITCH + (L & 8)) * 2;
    const uint32_t offT =
        (uint32_t)((L & 15) * PITCH + ((L & 16) ? 8 : 0)) * 2;

    // --- async weight prefetch: Wq -> W1, Wk -> W2 ---
    for (int i = tid; i < 2176; i += 256) {
        cp16(w1h_u + i * 16, (const char*)g_wh[0] + i * 16);
        cp16(w1l_u + i * 16, (const char*)g_wl[0] + i * 16);
        cp16(w2h_u + i * 16, (const char*)g_wh[1] + i * 16);
        cp16(w2l_u + i * 16, (const char*)g_wl[1] + i * 16);
    }
    CP_COMMIT();

    float* sgam = (float*)(smc + GB_OFF);
    float* sbet = sgam + 128;
    if (tid < 128) {
        sgam[tid] = gamma[tid];
        sbet[tid] = beta[tid];
    }

    // --- load X tile -> bf16 hi/lo pitched smem ---
    {
        unsigned short* XH = (unsigned short*)(smc + XH_OFF);
        unsigned short* XL = (unsigned short*)(smc + XL_OFF);
        const long long base =
            ((long long)blockIdx.y * 8192 + (long long)blockIdx.x * 128) * 128;
        const int row = tid >> 1, c0 = (tid & 1) * 64;
        const float4* xg = (const float4*)(x + base + row * 128 + c0);
#pragma unroll
        for (int i = 0; i < 16; ++i) {
            float4 f = xg[i];
            uint32_t h0, l0, h1, l1;
            split2(f.x, f.y, h0, l0);
            split2(f.z, f.w, h1, l1);
            *(uint32_t*)&XH[row * PITCH + c0 + 4 * i] = h0;
            *(uint32_t*)&XH[row * PITCH + c0 + 4 * i + 2] = h1;
            *(uint32_t*)&XL[row * PITCH + c0 + 4 * i] = l0;
            *(uint32_t*)&XL[row * PITCH + c0 + 4 * i + 2] = l1;
        }
    }
    CP_WAIT0();
    __syncthreads();

    float acc[16][4];
    uint32_t Ah[32], Al[32];
    const uint32_t aH = xh_u + (uint32_t)(R * PITCH) * 2 + offA;
    const uint32_t aL = xl_u + (uint32_t)(R * PITCH) * 2 + offA;

    // ---- Q = X @ Wq' (scale folded) ----
    gemm_sAB(aH, aL, w1h_u + offB, w1l_u + offB, acc);
    to_afrag(acc, Ah, Al);  // Q frags

    // ---- K = X @ Wk ----
    gemm_sAB(aH, aL, w2h_u + offB, w2l_u + offB, acc);
    __syncthreads();  // all W1 (Wq) / W2 (Wk) reads done

    // store K -> W1 region (bf16 hi/lo, row-major [tok][d])
    {
        unsigned short* KH = (unsigned short*)(smc + W1H_OFF);
        unsigned short* KL = (unsigned short*)(smc + W1L_OFF);
#pragma unroll
        for (int j = 0; j < 16; ++j) {
            const int col = 8 * j + 2 * t;
            uint32_t h, l;
            split2(acc[j][0], acc[j][1], h, l);
            *(uint32_t*)&KH[(R + g) * PITCH + col] = h;
            *(uint32_t*)&KL[(R + g) * PITCH + col] = l;
            split2(acc[j][2], acc[j][3], h, l);
            *(uint32_t*)&KH[(R + g + 8) * PITCH + col] = h;
            *(uint32_t*)&KL[(R + g + 8) * PITCH + col] = l;
        }
    }
    // async prefetch Wvo -> W2 (hidden behind S + softmax + T)
    for (int i = tid; i < 2176; i += 256) {
        cp16(w2h_u + i * 16, (const char*)g_wh[2] + i * 16);
        cp16(w2l_u + i * 16, (const char*)g_wl[2] + i * 16);
    }
    CP_COMMIT();
    __syncthreads();  // K visible

    // ---- S = Q @ K^T ----
    gemm_rAB(Ah, Al, w1h_u + offB, w1l_u + offB, acc);

    // ---- softmax per row ----
    {
        float mx0 = -1e30f, mx1 = -1e30f;
#pragma unroll
        for (int j = 0; j < 16; ++j) {
            mx0 = fmaxf(mx0, fmaxf(acc[j][0], acc[j][1]));
            mx1 = fmaxf(mx1, fmaxf(acc[j][2], acc[j][3]));
        }
        mx0 = fmaxf(mx0, __shfl_xor_sync(0xffffffffu, mx0, 1));
        mx0 = fmaxf(mx0, __shfl_xor_sync(0xffffffffu, mx0, 2));
        mx1 = fmaxf(mx1, __shfl_xor_sync(0xffffffffu, mx1, 1));
        mx1 = fmaxf(mx1, __shfl_xor_sync(0xffffffffu, mx1, 2));
        float s0 = 0.f, s1 = 0.f;
#pragma unroll
        for (int j = 0; j < 16; ++j) {
            acc[j][0] = __expf(acc[j][0] - mx0);
            acc[j][1] = __expf(acc[j][1] - mx0);
            acc[j][2] = __expf(acc[j][2] - mx1);
            acc[j][3] = __expf(acc[j][3] - mx1);
            s0 += acc[j][0] + acc[j][1];
            s1 += acc[j][2] + acc[j][3];
        }
        s0 += __shfl_xor_sync(0xffffffffu, s0, 1);
        s0 += __shfl_xor_sync(0xffffffffu, s0, 2);
        s1 += __shfl_xor_sync(0xffffffffu, s1, 1);
        s1 += __shfl_xor_sync(0xffffffffu, s1, 2);
        float i0 = 1.0f / s0, i1 = 1.0f / s1;
#pragma unroll
        for (int j = 0; j < 16; ++j) {
            acc[j][0] *= i0;
            acc[j][1] *= i0;
            acc[j][2] *= i1;
            acc[j][3] *= i1;
        }
    }
    to_afrag(acc, Ah, Al);  // P frags

    // ---- T = P @ X (ldmatrix.trans on X) ----
    gemm_rTX(Ah, Al, xh_u + offT, xl_u + offT, acc);
    to_afrag(acc, Ah, Al);  // T frags

    CP_WAIT0();
    __syncthreads();  // Wvo visible in W2

    // ---- H = T @ Wvo ----
    gemm_rAB(Ah, Al, w2h_u + offB, w2l_u + offB, acc);

    // ---- LayerNorm + exact GELU + store ----
    {
        float* sgamp = (float*)(smc + GB_OFF);
        float* sbetp = sgamp + 128;
        float s0 = 0.f, s1 = 0.f;
#pragma unroll
        for (int j = 0; j < 16; ++j) {
            s0 += acc[j][0] + acc[j][1];
            s1 += acc[j][2] + acc[j][3];
        }
        s0 += __shfl_xor_sync(0xffffffffu, s0, 1);
        s0 += __shfl_xor_sync(0xffffffffu, s0, 2);
        s1 += __shfl_xor_sync(0xffffffffu, s1, 1);
        s1 += __shfl_xor_sync(0xffffffffu, s1, 2);
        float mu0 = s0 * (1.0f / 128.0f), mu1 = s1 * (1.0f / 128.0f);
        float q0 = 0.f, q1 = 0.f;
#pragma unroll
        for (int j = 0; j < 16; ++j) {
            float d0 = acc[j][0] - mu0, d1 = acc[j][1] - mu0;
            float d2 = acc[j][2] - mu1, d3 = acc[j][3] - mu1;
            q0 += d0 * d0 + d1 * d1;
            q1 += d2 * d2 + d3 * d3;
        }
        q0 += __shfl_xor_sync(0xffffffffu, q0, 1);
        q0 += __shfl_xor_sync(0xffffffffu, q0, 2);
        q1 += __shfl_xor_sync(0xffffffffu, q1, 1);
        q1 += __shfl_xor_sync(0xffffffffu, q1, 2);
        float r0 = rsqrtf(q0 * (1.0f / 128.0f) + 1e-5f);
        float r1 = rsqrtf(q1 * (1.0f / 128.0f) + 1e-5f);

        float* orow = out + ((long long)blockIdx.y * 16384 +
                             (long long)blockIdx.x * 128 + R + g) * 128;
        float* orow8 = orow + 8 * 128;
#pragma unroll
        for (int j = 0; j < 16; ++j) {
            const int col = 8 * j + 2 * t;
            float ga0 = sgamp[col], ga1 = sgamp[col + 1];
            float be0 = sbetp[col], be1 = sbetp[col + 1];
            float y0 = (acc[j][0] - mu0) * r0 * ga0 + be0;
            float y1 = (acc[j][1] - mu0) * r0 * ga1 + be1;
            float y2 = (acc[j][2] - mu1) * r1 * ga0 + be0;
            float y3 = (acc[j][3] - mu1) * r1 * ga1 + be1;
            float2 o0, o1;
            o0.x = 0.5f * y0 * (1.f + erff(y0 * 0.70710678118654752f));
            o0.y = 0.5f * y1 * (1.f + erff(y1 * 0.70710678118654752f));
            o1.x = 0.5f * y2 * (1.f + erff(y2 * 0.70710678118654752f));
            o1.y = 0.5f * y3 * (1.f + erff(y3 * 0.70710678118654752f));
            *(float2*)&orow[col] = o0;
            *(float2*)&orow8[col] = o1;
        }
    }
}

// ---------------------------------------------------------------------------
extern "C" void kernel_launch(void* const* d_in, const int* in_sizes, int n_in,
                              void* d_out, int out_size) {
    const float* x     = (const float*)d_in[0];
    const float* Wq    = (const float*)d_in[1];
    const float* Wk    = (const float*)d_in[2];
    const float* Wv    = (const float*)d_in[3];
    const float* Wo    = (const float*)d_in[4];
    const float* gamma = (const float*)d_in[5];
    const float* beta  = (const float*)d_in[6];
    float* out = (float*)d_out;

    cudaFuncSetAttribute(attn_kernel,
                         cudaFuncAttributeMaxDynamicSharedMemorySize, SMEM_BYTES);

    wvo_kernel<<<128, 128>>>(Wv, Wo);
    prep_kernel<<<3, 128>>>(Wq, Wk);
    fill_kernel<<<2048, 256>>>(beta, out);
    attn_kernel<<<dim3(64, 8), 256, SMEM_BYTES>>>(x, gamma, beta, out);
}